// round 8
// baseline (speedup 1.0000x reference)
#include <cuda_runtime.h>
#include <cuda_bf16.h>
#include <math.h>
#include <stdint.h>

#define TT  8192
#define HH  1024
#define EE  8
#define CAP 1280
#define IRR 4096
#define ISS 8192

// per-buffer smem layout (bytes): A hi/lo 128 rows x 80B, B hi/lo 32 rows x 272B
#define A_HI 0
#define A_LO 10240
#define B_HI 20480
#define B_LO 29184
#define SM_BUF 37888
#define SM_TOT (2 * SM_BUF)

__device__ float g_sh[(size_t)TT * ISS];
__device__ float g_rb[(size_t)EE * CAP * IRR];
__device__ int   g_tki[TT * 2];
__device__ float g_tkw[TT * 2];
__device__ int   g_disp[EE * CAP];
__device__ float g_gw[EE * CAP];

__device__ __forceinline__ uint32_t smem_u32(const void* p) {
    uint32_t a;
    asm("{ .reg .u64 t; cvta.to.shared.u64 t, %1; cvt.u32.u64 %0, t; }" : "=r"(a) : "l"(p));
    return a;
}
__device__ __forceinline__ void ldsm4(uint32_t* r, uint32_t addr) {
    asm volatile("ldmatrix.sync.aligned.m8n8.x4.shared.b16 {%0,%1,%2,%3}, [%4];"
        : "=r"(r[0]), "=r"(r[1]), "=r"(r[2]), "=r"(r[3]) : "r"(addr));
}
__device__ __forceinline__ void ldsm4t(uint32_t* r, uint32_t addr) {
    asm volatile("ldmatrix.sync.aligned.m8n8.x4.trans.shared.b16 {%0,%1,%2,%3}, [%4];"
        : "=r"(r[0]), "=r"(r[1]), "=r"(r[2]), "=r"(r[3]) : "r"(addr));
}
__device__ __forceinline__ void mma16816(float* d, const uint32_t* a, uint32_t b0, uint32_t b1) {
    asm volatile("mma.sync.aligned.m16n8k16.row.col.f32.bf16.bf16.f32 "
        "{%0,%1,%2,%3}, {%4,%5,%6,%7}, {%8,%9}, {%0,%1,%2,%3};"
        : "+f"(d[0]), "+f"(d[1]), "+f"(d[2]), "+f"(d[3])
        : "r"(a[0]), "r"(a[1]), "r"(a[2]), "r"(a[3]), "r"(b0), "r"(b1));
}
__device__ __forceinline__ uint32_t b2u(__nv_bfloat162 v) { return *(uint32_t*)&v; }
__device__ __forceinline__ void cvt8(float4 v, uint2& h, uint2& l) {
    __nv_bfloat162 h0 = __floats2bfloat162_rn(v.x, v.y);
    __nv_bfloat162 h1 = __floats2bfloat162_rn(v.z, v.w);
    float rx = v.x - __bfloat162float(h0.x);
    float ry = v.y - __bfloat162float(h0.y);
    float rz = v.z - __bfloat162float(h1.x);
    float rw = v.w - __bfloat162float(h1.y);
    __nv_bfloat162 l0 = __floats2bfloat162_rn(rx, ry);
    __nv_bfloat162 l1 = __floats2bfloat162_rn(rz, rw);
    h.x = b2u(h0); h.y = b2u(h1);
    l.x = b2u(l0); l.y = b2u(l1);
}

__global__ void router_kernel(const float* __restrict__ x, const float* __restrict__ rw)
{
    int t = blockIdx.x;
    const float* xr = x + (size_t)t * HH;
    float ss = 0.f, dot[EE];
#pragma unroll
    for (int e = 0; e < EE; e++) dot[e] = 0.f;
    for (int i = threadIdx.x; i < HH; i += 256) {
        float v = xr[i];
        ss += v * v;
#pragma unroll
        for (int e = 0; e < EE; e++) dot[e] += v * rw[e * HH + i];
    }
#pragma unroll
    for (int off = 16; off > 0; off >>= 1) {
        ss += __shfl_down_sync(0xffffffffu, ss, off);
#pragma unroll
        for (int e = 0; e < EE; e++) dot[e] += __shfl_down_sync(0xffffffffu, dot[e], off);
    }
    __shared__ float red[8][9];
    int warp = threadIdx.x >> 5, lane = threadIdx.x & 31;
    if (lane == 0) {
        red[warp][0] = ss;
#pragma unroll
        for (int e = 0; e < EE; e++) red[warp][1 + e] = dot[e];
    }
    __syncthreads();
    if (threadIdx.x == 0) {
        float s = 0.f, d[EE];
#pragma unroll
        for (int e = 0; e < EE; e++) d[e] = 0.f;
        for (int w2 = 0; w2 < 8; w2++) {
            s += red[w2][0];
#pragma unroll
            for (int e = 0; e < EE; e++) d[e] += red[w2][1 + e];
        }
        float r = rsqrtf(s / (float)HH + 1.1920929e-7f);
        float lg[EE];
#pragma unroll
        for (int e = 0; e < EE; e++) lg[e] = d[e] * r;
        int i1 = 0;
        for (int e = 1; e < EE; e++) if (lg[e] > lg[i1]) i1 = e;
        int i2 = -1;
        for (int e = 0; e < EE; e++) {
            if (e == i1) continue;
            if (i2 < 0 || lg[e] > lg[i2]) i2 = e;
        }
        float e2 = expf(lg[i2] - lg[i1]);
        float inv = 1.f / (1.f + e2);
        g_tki[t * 2] = i1; g_tki[t * 2 + 1] = i2;
        g_tkw[t * 2] = inv; g_tkw[t * 2 + 1] = e2 * inv;
    }
}

__global__ void dispatch_kernel()
{
    int e = blockIdx.x, tid = threadIdx.x;
    __shared__ int scan[256];
    __shared__ int base_s;
    for (int s = tid; s < CAP; s += 256) { g_disp[e*CAP+s] = 0; g_gw[e*CAP+s] = 0.f; }
    if (tid == 0) base_s = 0;
    __syncthreads();
    for (int c0 = 0; c0 < TT; c0 += 256) {
        int t = c0 + tid;
        int i0 = g_tki[t*2], i1 = g_tki[t*2+1];
        float wt = (i0 == e) ? g_tkw[t*2] : ((i1 == e) ? g_tkw[t*2+1] : 0.f);
        int sel = (i0 == e) || (i1 == e);
        scan[tid] = sel;
        __syncthreads();
        for (int off = 1; off < 256; off <<= 1) {
            int v = (tid >= off) ? scan[tid - off] : 0;
            __syncthreads();
            scan[tid] += v;
            __syncthreads();
        }
        int slot = base_s + scan[tid] - 1;
        if (sel && slot < CAP) { g_disp[e*CAP+slot] = t; g_gw[e*CAP+slot] = wt; }
        __syncthreads();
        if (tid == 0) base_s += scan[255];
        __syncthreads();
    }
}

// C[M,N] = A[M,K] @ B[K,N]. 512 threads, 128x128 tile, warp tile 64x16,
// double-buffered smem, bf16 mma.sync 3-term hi/lo split.
template <bool GATHER, int EPI>
__global__ void __launch_bounds__(512, 1) hgemm_k(
    const float* __restrict__ A, const float* __restrict__ B, float* __restrict__ C,
    int Kd, int N, size_t sA, size_t sB, size_t sC,
    const int* __restrict__ disp, const float* __restrict__ wv,
    float* __restrict__ outp)
{
    extern __shared__ char smem[];
    uint32_t sb = smem_u32(smem);
    int tid = threadIdx.x, wid = tid >> 5, lane = tid & 31;
    int z = blockIdx.z;
    int bm = blockIdx.y * 128, bn = blockIdx.x * 128;
    int wm = wid & 1, wn = wid >> 1;     // warp tile: 64 (M) x 16 (N)

    // loader mapping: A 128 rows x 32 f32, 4 threads/row (8 f32 each)
    int arw = tid >> 2, aq = tid & 3;
    // B: 32 k-rows x 128 f32, 16 threads/row (8 f32 each)
    int bkr = tid >> 4, bseg = tid & 15;
    const float* aptr;
    if (GATHER) aptr = A + (size_t)disp[z * CAP + bm + arw] * Kd + aq * 8;
    else        aptr = A + (size_t)z * sA + (size_t)(bm + arw) * Kd + aq * 8;
    const float* bptr = B + (size_t)z * sB + (size_t)bkr * N + bn + bseg * 8;
    uint32_t a_st = (uint32_t)arw * 80u + (uint32_t)aq * 16u;
    uint32_t b_st = B_HI + (uint32_t)bkr * 272u + (uint32_t)bseg * 16u;

    // ldmatrix lane address bases
    int li = lane & 15, kh = (lane >> 4) << 3;
    uint32_t a_ld = sb + (uint32_t)(wm * 64 + li) * 80u + (uint32_t)kh * 2u;
    uint32_t b_ld = sb + B_HI + (uint32_t)li * 272u + (uint32_t)(wn * 16 + kh) * 2u;

    float acc[4][2][4];
#pragma unroll
    for (int i = 0; i < 4; i++)
#pragma unroll
        for (int j = 0; j < 2; j++)
#pragma unroll
            for (int c = 0; c < 4; c++) acc[i][j][c] = 0.f;

    const int NIT = Kd / 32;
    float4 ra[2], rb[2];
#pragma unroll
    for (int i = 0; i < 2; i++) {
        ra[i] = *(const float4*)(aptr + i * 4);
        rb[i] = *(const float4*)(bptr + i * 4);
    }
    // store chunk 0 into buffer 0
    {
        uint2 h, l;
#pragma unroll
        for (int i = 0; i < 2; i++) {
            cvt8(ra[i], h, l);
            *(uint2*)(smem + a_st + i * 8) = h;
            *(uint2*)(smem + a_st + A_LO + i * 8) = l;
            cvt8(rb[i], h, l);
            *(uint2*)(smem + b_st + i * 8) = h;
            *(uint2*)(smem + b_st + (B_LO - B_HI) + i * 8) = l;
        }
    }
    __syncthreads();

    for (int it = 0; it < NIT; it++) {
        // prefetch next chunk into regs (hidden under MMA)
        if (it + 1 < NIT) {
            int k0 = (it + 1) * 32;
#pragma unroll
            for (int i = 0; i < 2; i++) {
                ra[i] = *(const float4*)(aptr + k0 + i * 4);
                rb[i] = *(const float4*)(bptr + (size_t)k0 * N + i * 4);
            }
        }
        uint32_t bo = (uint32_t)(it & 1) * SM_BUF;
        // compute two k16 steps on current buffer
#pragma unroll
        for (int k0 = 0; k0 < 32; k0 += 16) {
            uint32_t ah[4][4], al[4][4], bh[4], bl[4];
#pragma unroll
            for (int mt = 0; mt < 4; mt++) {
                uint32_t ad = a_ld + bo + (uint32_t)mt * 1280u + (uint32_t)k0 * 2u;
                ldsm4(ah[mt], ad);
                ldsm4(al[mt], ad + A_LO);
            }
            uint32_t bd = b_ld + bo + (uint32_t)k0 * 272u;
            ldsm4t(bh, bd);
            ldsm4t(bl, bd + (B_LO - B_HI));
#pragma unroll
            for (int mt = 0; mt < 4; mt++)
#pragma unroll
                for (int nt = 0; nt < 2; nt++) {
                    mma16816(acc[mt][nt], ah[mt], bh[nt * 2], bh[nt * 2 + 1]);
                    mma16816(acc[mt][nt], ah[mt], bl[nt * 2], bl[nt * 2 + 1]);
                    mma16816(acc[mt][nt], al[mt], bh[nt * 2], bh[nt * 2 + 1]);
                }
        }
        // store prefetched chunk into other buffer, single sync per iter
        if (it + 1 < NIT) {
            uint32_t so = (uint32_t)((it + 1) & 1) * SM_BUF;
            uint2 h, l;
#pragma unroll
            for (int i = 0; i < 2; i++) {
                cvt8(ra[i], h, l);
                *(uint2*)(smem + so + a_st + i * 8) = h;
                *(uint2*)(smem + so + a_st + A_LO + i * 8) = l;
                cvt8(rb[i], h, l);
                *(uint2*)(smem + so + b_st + i * 8) = h;
                *(uint2*)(smem + so + b_st + (B_LO - B_HI) + i * 8) = l;
            }
            __syncthreads();
        }
    }

    // epilogue: per mma tile, lane owns (row g, col c..c+1) and (row g+8, same cols)
    int g = lane >> 2, tg = lane & 3;
#pragma unroll
    for (int mt = 0; mt < 4; mt++) {
#pragma unroll
        for (int nt = 0; nt < 2; nt++) {
            int row0 = bm + wm * 64 + mt * 16 + g;
            int col = bn + wn * 16 + nt * 8 + tg * 2;
            float* d = acc[mt][nt];
            if (EPI == 0) {
                float* p0 = C + (size_t)z * sC + (size_t)row0 * N + col;
                float* p1 = p0 + (size_t)8 * N;
                *(float2*)p0 = make_float2(d[0], d[1]);
                *(float2*)p1 = make_float2(d[2], d[3]);
            } else if (EPI == 1) {
                float* p0 = C + (size_t)z * sC + (size_t)row0 * N + col;
                float* p1 = p0 + (size_t)8 * N;
                float2 g0 = *(float2*)p0;
                float2 g1 = *(float2*)p1;
                float2 o0, o1;
                o0.x = g0.x / (1.f + expf(-g0.x)) * d[0];
                o0.y = g0.y / (1.f + expf(-g0.y)) * d[1];
                o1.x = g1.x / (1.f + expf(-g1.x)) * d[2];
                o1.y = g1.y / (1.f + expf(-g1.y)) * d[3];
                *(float2*)p0 = o0;
                *(float2*)p1 = o1;
            } else {
                int s0 = z * CAP + row0, s1 = s0 + 8;
                int t0 = disp[s0], t1 = disp[s1];
                float w0 = wv[s0], w1 = wv[s1];
                float* p0 = outp + (size_t)t0 * HH + col;
                float* p1 = outp + (size_t)t1 * HH + col;
                atomicAdd(p0 + 0, w0 * d[0]);
                atomicAdd(p0 + 1, w0 * d[1]);
                atomicAdd(p1 + 0, w1 * d[2]);
                atomicAdd(p1 + 1, w1 * d[3]);
            }
        }
    }
}

extern "C" void kernel_launch(void* const* d_in, const int* in_sizes, int n_in,
                              void* d_out, int out_size)
{
    const float* x  = (const float*)d_in[0];
    const float* rw = (const float*)d_in[1];
    const float* rg = (const float*)d_in[2];
    const float* ru = (const float*)d_in[3];
    const float* rd = (const float*)d_in[4];
    const float* sg = (const float*)d_in[5];
    const float* su = (const float*)d_in[6];
    const float* sd = (const float*)d_in[7];
    float* out = (float*)d_out;

    float *p_sh, *p_rb, *p_gw;
    int *p_disp;
    cudaGetSymbolAddress((void**)&p_sh, g_sh);
    cudaGetSymbolAddress((void**)&p_rb, g_rb);
    cudaGetSymbolAddress((void**)&p_gw, g_gw);
    cudaGetSymbolAddress((void**)&p_disp, g_disp);

    cudaFuncSetAttribute(hgemm_k<false,0>, cudaFuncAttributeMaxDynamicSharedMemorySize, SM_TOT);
    cudaFuncSetAttribute(hgemm_k<false,1>, cudaFuncAttributeMaxDynamicSharedMemorySize, SM_TOT);
    cudaFuncSetAttribute(hgemm_k<false,2>, cudaFuncAttributeMaxDynamicSharedMemorySize, SM_TOT);
    cudaFuncSetAttribute(hgemm_k<true,0>,  cudaFuncAttributeMaxDynamicSharedMemorySize, SM_TOT);
    cudaFuncSetAttribute(hgemm_k<true,1>,  cudaFuncAttributeMaxDynamicSharedMemorySize, SM_TOT);

    router_kernel<<<TT, 256>>>(x, rw);
    dispatch_kernel<<<EE, 256>>>();

    // shared expert
    dim3 gsh(ISS / 128, TT / 128);
    hgemm_k<false, 0><<<gsh, 512, SM_TOT>>>(x, sg, p_sh, HH, ISS, 0, 0, 0, (const int*)0, (const float*)0, (float*)0);
    hgemm_k<false, 1><<<gsh, 512, SM_TOT>>>(x, su, p_sh, HH, ISS, 0, 0, 0, (const int*)0, (const float*)0, (float*)0);
    dim3 gsd(HH / 128, TT / 128);
    hgemm_k<false, 0><<<gsd, 512, SM_TOT>>>(p_sh, sd, out, ISS, HH, 0, 0, 0, (const int*)0, (const float*)0, (float*)0);

    // routed experts
    dim3 grt(IRR / 128, CAP / 128, EE);
    hgemm_k<true, 0><<<grt, 512, SM_TOT>>>(x, rg, p_rb, HH, IRR,
                                           0, (size_t)HH * IRR, (size_t)CAP * IRR,
                                           p_disp, (const float*)0, (float*)0);
    hgemm_k<true, 1><<<grt, 512, SM_TOT>>>(x, ru, p_rb, HH, IRR,
                                           0, (size_t)HH * IRR, (size_t)CAP * IRR,
                                           p_disp, (const float*)0, (float*)0);

    dim3 grd(HH / 128, CAP / 128, EE);
    hgemm_k<false, 2><<<grd, 512, SM_TOT>>>(p_rb, rd, (float*)0, IRR, HH,
                                            (size_t)CAP * IRR, (size_t)IRR * HH, 0,
                                            p_disp, p_gw, out);
}

// round 9
// speedup vs baseline: 1.2115x; 1.2115x over previous
#include <cuda_runtime.h>
#include <cuda_bf16.h>
#include <math.h>
#include <stdint.h>

#define TT  8192
#define HH  1024
#define EE  8
#define CAP 1280
#define IRR 4096
#define ISS 8192

// per-buffer smem layout (bytes): A hi/lo 128 rows x 80B, B hi/lo 32 rows x 272B
#define A_HI 0
#define A_LO 10240
#define B_HI 20480
#define B_LO 29184
#define SM_BUF 37888
#define SM_TOT (2 * SM_BUF)

__device__ float g_sh[(size_t)TT * ISS];
__device__ float g_rb[(size_t)EE * CAP * IRR];
__device__ int   g_tki[TT * 2];
__device__ float g_tkw[TT * 2];
__device__ int   g_disp[EE * CAP];
__device__ float g_gw[EE * CAP];

__device__ __forceinline__ uint32_t smem_u32(const void* p) {
    uint32_t a;
    asm("{ .reg .u64 t; cvta.to.shared.u64 t, %1; cvt.u32.u64 %0, t; }" : "=r"(a) : "l"(p));
    return a;
}
__device__ __forceinline__ void ldsm4(uint32_t* r, uint32_t addr) {
    asm volatile("ldmatrix.sync.aligned.m8n8.x4.shared.b16 {%0,%1,%2,%3}, [%4];"
        : "=r"(r[0]), "=r"(r[1]), "=r"(r[2]), "=r"(r[3]) : "r"(addr));
}
__device__ __forceinline__ void ldsm4t(uint32_t* r, uint32_t addr) {
    asm volatile("ldmatrix.sync.aligned.m8n8.x4.trans.shared.b16 {%0,%1,%2,%3}, [%4];"
        : "=r"(r[0]), "=r"(r[1]), "=r"(r[2]), "=r"(r[3]) : "r"(addr));
}
__device__ __forceinline__ void mma16816(float* d, const uint32_t* a, uint32_t b0, uint32_t b1) {
    asm volatile("mma.sync.aligned.m16n8k16.row.col.f32.bf16.bf16.f32 "
        "{%0,%1,%2,%3}, {%4,%5,%6,%7}, {%8,%9}, {%0,%1,%2,%3};"
        : "+f"(d[0]), "+f"(d[1]), "+f"(d[2]), "+f"(d[3])
        : "r"(a[0]), "r"(a[1]), "r"(a[2]), "r"(a[3]), "r"(b0), "r"(b1));
}
__device__ __forceinline__ uint32_t b2u(__nv_bfloat162 v) { return *(uint32_t*)&v; }
__device__ __forceinline__ void cvt8(float4 v, uint2& h, uint2& l) {
    __nv_bfloat162 h0 = __floats2bfloat162_rn(v.x, v.y);
    __nv_bfloat162 h1 = __floats2bfloat162_rn(v.z, v.w);
    float rx = v.x - __bfloat162float(h0.x);
    float ry = v.y - __bfloat162float(h0.y);
    float rz = v.z - __bfloat162float(h1.x);
    float rw = v.w - __bfloat162float(h1.y);
    __nv_bfloat162 l0 = __floats2bfloat162_rn(rx, ry);
    __nv_bfloat162 l1 = __floats2bfloat162_rn(rz, rw);
    h.x = b2u(h0); h.y = b2u(h1);
    l.x = b2u(l0); l.y = b2u(l1);
}

__global__ void router_kernel(const float* __restrict__ x, const float* __restrict__ rw)
{
    int t = blockIdx.x;
    const float* xr = x + (size_t)t * HH;
    float ss = 0.f, dot[EE];
#pragma unroll
    for (int e = 0; e < EE; e++) dot[e] = 0.f;
    for (int i = threadIdx.x; i < HH; i += 256) {
        float v = xr[i];
        ss += v * v;
#pragma unroll
        for (int e = 0; e < EE; e++) dot[e] += v * rw[e * HH + i];
    }
#pragma unroll
    for (int off = 16; off > 0; off >>= 1) {
        ss += __shfl_down_sync(0xffffffffu, ss, off);
#pragma unroll
        for (int e = 0; e < EE; e++) dot[e] += __shfl_down_sync(0xffffffffu, dot[e], off);
    }
    __shared__ float red[8][9];
    int warp = threadIdx.x >> 5, lane = threadIdx.x & 31;
    if (lane == 0) {
        red[warp][0] = ss;
#pragma unroll
        for (int e = 0; e < EE; e++) red[warp][1 + e] = dot[e];
    }
    __syncthreads();
    if (threadIdx.x == 0) {
        float s = 0.f, d[EE];
#pragma unroll
        for (int e = 0; e < EE; e++) d[e] = 0.f;
        for (int w2 = 0; w2 < 8; w2++) {
            s += red[w2][0];
#pragma unroll
            for (int e = 0; e < EE; e++) d[e] += red[w2][1 + e];
        }
        float r = rsqrtf(s / (float)HH + 1.1920929e-7f);
        float lg[EE];
#pragma unroll
        for (int e = 0; e < EE; e++) lg[e] = d[e] * r;
        int i1 = 0;
        for (int e = 1; e < EE; e++) if (lg[e] > lg[i1]) i1 = e;
        int i2 = -1;
        for (int e = 0; e < EE; e++) {
            if (e == i1) continue;
            if (i2 < 0 || lg[e] > lg[i2]) i2 = e;
        }
        float e2 = expf(lg[i2] - lg[i1]);
        float inv = 1.f / (1.f + e2);
        g_tki[t * 2] = i1; g_tki[t * 2 + 1] = i2;
        g_tkw[t * 2] = inv; g_tkw[t * 2 + 1] = e2 * inv;
    }
}

__global__ void dispatch_kernel()
{
    int e = blockIdx.x, tid = threadIdx.x;
    __shared__ int scan[256];
    __shared__ int base_s;
    for (int s = tid; s < CAP; s += 256) { g_disp[e*CAP+s] = 0; g_gw[e*CAP+s] = 0.f; }
    if (tid == 0) base_s = 0;
    __syncthreads();
    for (int c0 = 0; c0 < TT; c0 += 256) {
        int t = c0 + tid;
        int i0 = g_tki[t*2], i1 = g_tki[t*2+1];
        float wt = (i0 == e) ? g_tkw[t*2] : ((i1 == e) ? g_tkw[t*2+1] : 0.f);
        int sel = (i0 == e) || (i1 == e);
        scan[tid] = sel;
        __syncthreads();
        for (int off = 1; off < 256; off <<= 1) {
            int v = (tid >= off) ? scan[tid - off] : 0;
            __syncthreads();
            scan[tid] += v;
            __syncthreads();
        }
        int slot = base_s + scan[tid] - 1;
        if (sel && slot < CAP) { g_disp[e*CAP+slot] = t; g_gw[e*CAP+slot] = wt; }
        __syncthreads();
        if (tid == 0) base_s += scan[255];
        __syncthreads();
    }
}

// C[M,N] = A[M,K] @ B[K,N]. 256 threads, 128x128 tile, warp tile 64x32,
// DOUBLE-buffered smem, bf16 mma.sync 3-term hi/lo split.
template <bool GATHER, int EPI>
__global__ void __launch_bounds__(256, 1) hgemm_k(
    const float* __restrict__ A, const float* __restrict__ B, float* __restrict__ C,
    int Kd, int N, size_t sA, size_t sB, size_t sC,
    const int* __restrict__ disp, const float* __restrict__ wv,
    float* __restrict__ outp)
{
    extern __shared__ char smem[];
    uint32_t sb = smem_u32(smem);
    int tid = threadIdx.x, wid = tid >> 5, lane = tid & 31;
    int z = blockIdx.z;
    int bm = blockIdx.y * 128, bn = blockIdx.x * 128;
    int wm = wid & 1, wn = wid >> 1;     // warp tile: 64 (M) x 32 (N)

    // loader mapping (identical to R7)
    int arw = tid >> 1, ahalf = tid & 1;         // A: 128 rows, 2 half-rows of 16 f32
    int bkr = tid >> 3, bseg = tid & 7;          // B: 32 k-rows, 8 segs of 16 f32
    const float* aptr;
    if (GATHER) aptr = A + (size_t)disp[z * CAP + bm + arw] * Kd + ahalf * 16;
    else        aptr = A + (size_t)z * sA + (size_t)(bm + arw) * Kd + ahalf * 16;
    const float* bptr = B + (size_t)z * sB + (size_t)bkr * N + bn + bseg * 16;
    uint32_t a_st = (uint32_t)arw * 80u + (uint32_t)ahalf * 32u;
    uint32_t b_st = B_HI + (uint32_t)bkr * 272u + (uint32_t)bseg * 32u;

    // ldmatrix lane address bases
    int li = lane & 15, kh = (lane >> 4) << 3;
    uint32_t a_ld = sb + (uint32_t)(wm * 64 + li) * 80u + (uint32_t)kh * 2u;
    uint32_t b_ld = sb + B_HI + (uint32_t)li * 272u + (uint32_t)(wn * 32 + kh) * 2u;

    float acc[4][4][4];
#pragma unroll
    for (int i = 0; i < 4; i++)
#pragma unroll
        for (int j = 0; j < 4; j++)
#pragma unroll
            for (int c = 0; c < 4; c++) acc[i][j][c] = 0.f;

    const int NIT = Kd / 32;
    float4 ra[4], rb[4];
#pragma unroll
    for (int i = 0; i < 4; i++) {
        ra[i] = *(const float4*)(aptr + i * 4);
        rb[i] = *(const float4*)(bptr + i * 4);
    }
    // store chunk 0 into buffer 0
    {
        uint2 h, l;
#pragma unroll
        for (int i = 0; i < 4; i++) {
            cvt8(ra[i], h, l);
            *(uint2*)(smem + a_st + i * 8) = h;
            *(uint2*)(smem + a_st + A_LO + i * 8) = l;
            cvt8(rb[i], h, l);
            *(uint2*)(smem + b_st + i * 8) = h;
            *(uint2*)(smem + b_st + (B_LO - B_HI) + i * 8) = l;
        }
    }
    __syncthreads();

    for (int it = 0; it < NIT; it++) {
        // issue global prefetch of next chunk first (latency hidden under MMA)
        if (it + 1 < NIT) {
            int k0 = (it + 1) * 32;
#pragma unroll
            for (int i = 0; i < 4; i++) {
                ra[i] = *(const float4*)(aptr + k0 + i * 4);
                rb[i] = *(const float4*)(bptr + (size_t)k0 * N + i * 4);
            }
        }
        uint32_t bo = (uint32_t)(it & 1) * SM_BUF;
        // compute two k16 steps on current buffer
#pragma unroll
        for (int k0 = 0; k0 < 32; k0 += 16) {
            uint32_t ah[4][4], al[4][4], bh[2][4], bl[2][4];
#pragma unroll
            for (int mt = 0; mt < 4; mt++) {
                uint32_t ad = a_ld + bo + (uint32_t)mt * 1280u + (uint32_t)k0 * 2u;
                ldsm4(ah[mt], ad);
                ldsm4(al[mt], ad + A_LO);
            }
#pragma unroll
            for (int np = 0; np < 2; np++) {
                uint32_t bd = b_ld + bo + (uint32_t)k0 * 272u + (uint32_t)np * 32u;
                ldsm4t(bh[np], bd);
                ldsm4t(bl[np], bd + (B_LO - B_HI));
            }
#pragma unroll
            for (int mt = 0; mt < 4; mt++)
#pragma unroll
                for (int nt = 0; nt < 4; nt++) {
                    int np = nt >> 1, r = (nt & 1) * 2;
                    mma16816(acc[mt][nt], ah[mt], bh[np][r], bh[np][r + 1]);
                    mma16816(acc[mt][nt], ah[mt], bl[np][r], bl[np][r + 1]);
                    mma16816(acc[mt][nt], al[mt], bh[np][r], bh[np][r + 1]);
                }
        }
        // store prefetched chunk into the other buffer; single sync per iter
        if (it + 1 < NIT) {
            uint32_t so = (uint32_t)((it + 1) & 1) * SM_BUF;
            uint2 h, l;
#pragma unroll
            for (int i = 0; i < 4; i++) {
                cvt8(ra[i], h, l);
                *(uint2*)(smem + so + a_st + i * 8) = h;
                *(uint2*)(smem + so + a_st + A_LO + i * 8) = l;
                cvt8(rb[i], h, l);
                *(uint2*)(smem + so + b_st + i * 8) = h;
                *(uint2*)(smem + so + b_st + (B_LO - B_HI) + i * 8) = l;
            }
            __syncthreads();
        }
    }

    // epilogue (identical to R7)
    int g = lane >> 2, tg = lane & 3;
#pragma unroll
    for (int mt = 0; mt < 4; mt++) {
#pragma unroll
        for (int nt = 0; nt < 4; nt++) {
            int row0 = bm + wm * 64 + mt * 16 + g;
            int col = bn + wn * 32 + nt * 8 + tg * 2;
            float* d = acc[mt][nt];
            if (EPI == 0) {
                float* p0 = C + (size_t)z * sC + (size_t)row0 * N + col;
                float* p1 = p0 + (size_t)8 * N;
                *(float2*)p0 = make_float2(d[0], d[1]);
                *(float2*)p1 = make_float2(d[2], d[3]);
            } else if (EPI == 1) {
                float* p0 = C + (size_t)z * sC + (size_t)row0 * N + col;
                float* p1 = p0 + (size_t)8 * N;
                float2 g0 = *(float2*)p0;
                float2 g1 = *(float2*)p1;
                float2 o0, o1;
                o0.x = g0.x / (1.f + expf(-g0.x)) * d[0];
                o0.y = g0.y / (1.f + expf(-g0.y)) * d[1];
                o1.x = g1.x / (1.f + expf(-g1.x)) * d[2];
                o1.y = g1.y / (1.f + expf(-g1.y)) * d[3];
                *(float2*)p0 = o0;
                *(float2*)p1 = o1;
            } else {
                int s0 = z * CAP + row0, s1 = s0 + 8;
                int t0 = disp[s0], t1 = disp[s1];
                float w0 = wv[s0], w1 = wv[s1];
                float* p0 = outp + (size_t)t0 * HH + col;
                float* p1 = outp + (size_t)t1 * HH + col;
                atomicAdd(p0 + 0, w0 * d[0]);
                atomicAdd(p0 + 1, w0 * d[1]);
                atomicAdd(p1 + 0, w1 * d[2]);
                atomicAdd(p1 + 1, w1 * d[3]);
            }
        }
    }
}

extern "C" void kernel_launch(void* const* d_in, const int* in_sizes, int n_in,
                              void* d_out, int out_size)
{
    const float* x  = (const float*)d_in[0];
    const float* rw = (const float*)d_in[1];
    const float* rg = (const float*)d_in[2];
    const float* ru = (const float*)d_in[3];
    const float* rd = (const float*)d_in[4];
    const float* sg = (const float*)d_in[5];
    const float* su = (const float*)d_in[6];
    const float* sd = (const float*)d_in[7];
    float* out = (float*)d_out;

    float *p_sh, *p_rb, *p_gw;
    int *p_disp;
    cudaGetSymbolAddress((void**)&p_sh, g_sh);
    cudaGetSymbolAddress((void**)&p_rb, g_rb);
    cudaGetSymbolAddress((void**)&p_gw, g_gw);
    cudaGetSymbolAddress((void**)&p_disp, g_disp);

    cudaFuncSetAttribute(hgemm_k<false,0>, cudaFuncAttributeMaxDynamicSharedMemorySize, SM_TOT);
    cudaFuncSetAttribute(hgemm_k<false,1>, cudaFuncAttributeMaxDynamicSharedMemorySize, SM_TOT);
    cudaFuncSetAttribute(hgemm_k<false,2>, cudaFuncAttributeMaxDynamicSharedMemorySize, SM_TOT);
    cudaFuncSetAttribute(hgemm_k<true,0>,  cudaFuncAttributeMaxDynamicSharedMemorySize, SM_TOT);
    cudaFuncSetAttribute(hgemm_k<true,1>,  cudaFuncAttributeMaxDynamicSharedMemorySize, SM_TOT);

    router_kernel<<<TT, 256>>>(x, rw);
    dispatch_kernel<<<EE, 256>>>();

    // shared expert
    dim3 gsh(ISS / 128, TT / 128);
    hgemm_k<false, 0><<<gsh, 256, SM_TOT>>>(x, sg, p_sh, HH, ISS, 0, 0, 0, (const int*)0, (const float*)0, (float*)0);
    hgemm_k<false, 1><<<gsh, 256, SM_TOT>>>(x, su, p_sh, HH, ISS, 0, 0, 0, (const int*)0, (const float*)0, (float*)0);
    dim3 gsd(HH / 128, TT / 128);
    hgemm_k<false, 0><<<gsd, 256, SM_TOT>>>(p_sh, sd, out, ISS, HH, 0, 0, 0, (const int*)0, (const float*)0, (float*)0);

    // routed experts
    dim3 grt(IRR / 128, CAP / 128, EE);
    hgemm_k<true, 0><<<grt, 256, SM_TOT>>>(x, rg, p_rb, HH, IRR,
                                           0, (size_t)HH * IRR, (size_t)CAP * IRR,
                                           p_disp, (const float*)0, (float*)0);
    hgemm_k<true, 1><<<grt, 256, SM_TOT>>>(x, ru, p_rb, HH, IRR,
                                           0, (size_t)HH * IRR, (size_t)CAP * IRR,
                                           p_disp, (const float*)0, (float*)0);

    dim3 grd(HH / 128, CAP / 128, EE);
    hgemm_k<false, 2><<<grd, 256, SM_TOT>>>(p_rb, rd, (float*)0, IRR, HH,
                                            (size_t)CAP * IRR, (size_t)IRR * HH, 0,
                                            p_disp, p_gw, out);
}